// round 1
// baseline (speedup 1.0000x reference)
#include <cuda_runtime.h>
#include <math.h>

// Problem constants (fixed by setup_inputs: B=128, S=300, G=100)
#define S_MAX 300
#define G_MAX 100
#define B_MAX 128
#define NTHREADS 320
#define NWARPS (NTHREADS / 32)

#define CLASS_W 1.0
#define COORD_W 5.0
#define WIDTH_W 2.0
#define P0_W    2.0

static __device__ double g_C[B_MAX * G_MAX * S_MAX];   // cost matrices (double, ~31MB)
static __device__ double g_part[B_MAX * 5];            // per-batch partials

#define INF_D 1e300

__global__ __launch_bounds__(NTHREADS, 1)
void detr_batch_kernel(const float* __restrict__ strokes,
                       const float* __restrict__ logits,
                       const float* __restrict__ tparams,
                       const int*   __restrict__ tlabels)
{
    const int b   = blockIdx.x;
    const int tid = threadIdx.x;

    __shared__ double sh_shortest[S_MAX];
    __shared__ double sh_v[S_MAX];
    __shared__ double sh_u[G_MAX];
    __shared__ int    sh_path[S_MAX];
    __shared__ int    sh_row4col[S_MAX];
    __shared__ int    sh_col4row[G_MAX];
    __shared__ unsigned char sh_SC[S_MAX];
    __shared__ int    sh_SR[G_MAX + 2];
    __shared__ int    sh_valid[G_MAX];
    __shared__ int    sh_cls[G_MAX];
    __shared__ float  sh_prob[S_MAX * 3];
    __shared__ int    sh_tc[S_MAX];
    __shared__ int    sh_nv, sh_SRlen, sh_i, sh_sink;
    __shared__ double sh_minVal;
    __shared__ double sh_wv[NWARPS];
    __shared__ int    sh_wi[NWARPS];
    __shared__ double sh_acc[NWARPS];

    // ---- Phase 0: valid target list (order-preserving), tc init ----
    if (tid == 0) {
        int nv = 0;
        const int* lb = tlabels + (size_t)b * G_MAX;
        for (int g = 0; g < G_MAX; g++) {
            int l = lb[g];
            if (l > 0) { sh_valid[nv] = g; sh_cls[nv] = l; nv++; }
        }
        sh_nv = nv;
    }
    for (int j = tid; j < S_MAX; j += NTHREADS) {
        sh_tc[j] = 0;
        sh_v[j] = 0.0;
        sh_row4col[j] = -1;
    }
    for (int i = tid; i < G_MAX; i += NTHREADS) {
        sh_u[i] = 0.0;
        sh_col4row[i] = -1;
    }

    // ---- Phase 1a: softmax probs (f32, like jax) ----
    for (int j = tid; j < S_MAX; j += NTHREADS) {
        const float* lg = logits + ((size_t)b * S_MAX + j) * 3;
        float l0 = lg[0], l1 = lg[1], l2 = lg[2];
        float mx = fmaxf(l0, fmaxf(l1, l2));
        float e0 = expf(l0 - mx), e1 = expf(l1 - mx), e2 = expf(l2 - mx);
        float s = e0 + e1 + e2;
        sh_prob[j * 3 + 0] = e0 / s;
        sh_prob[j * 3 + 1] = e1 / s;
        sh_prob[j * 3 + 2] = e2 / s;
    }
    __syncthreads();

    const int nv = sh_nv;

    // ---- Phase 1b: cost matrix (double, matches reference float64 math) ----
    for (int idx = tid; idx < nv * S_MAX; idx += NTHREADS) {
        int i = idx / S_MAX;
        int j = idx - i * S_MAX;
        const float* sp = strokes + ((size_t)b * S_MAX + j) * 10;
        const float* tp = tparams + ((size_t)b * G_MAX + sh_valid[i]) * 10;
        double sum8 = 0.0;
        #pragma unroll
        for (int k = 0; k < 8; k++)
            sum8 += fabs((double)sp[k] - (double)tp[k]);
        double wsum = fabs((double)sp[8] - (double)tp[8])
                    + fabs((double)sp[9] - (double)tp[9]);
        double p0 = fabs((double)sp[0] - (double)tp[0])
                  + fabs((double)sp[1] - (double)tp[1]);
        double cc = -(double)sh_prob[j * 3 + sh_cls[i]];
        double C = ((CLASS_W * cc + COORD_W * sum8) + WIDTH_W * wsum) + P0_W * p0;
        g_C[((size_t)b * G_MAX + i) * S_MAX + j] = C;
    }
    __syncthreads();

    // ---- Phase 2: Jonker-Volgenant LAP (n=nv rows over m=300 cols) ----
    for (int cur = 0; cur < nv; cur++) {
        for (int j = tid; j < S_MAX; j += NTHREADS) {
            sh_shortest[j] = INF_D;
            sh_path[j] = -1;
            sh_SC[j] = 0;
        }
        if (tid == 0) { sh_SRlen = 0; sh_minVal = 0.0; sh_i = cur; sh_sink = -1; }
        __syncthreads();

        while (true) {
            int i = sh_i;
            double minVal = sh_minVal;
            double u_i = sh_u[i];

            double myval = INF_D;
            int myidx = 0x7fffffff;
            if (tid < S_MAX) {
                if (!sh_SC[tid]) {
                    double d = ((minVal + g_C[((size_t)b * G_MAX + i) * S_MAX + tid]) - u_i) - sh_v[tid];
                    if (d < sh_shortest[tid]) { sh_shortest[tid] = d; sh_path[tid] = i; }
                    myval = sh_shortest[tid];
                    myidx = tid;
                }
            }
            // warp argmin (tie -> lowest index, matching np.argmin)
            #pragma unroll
            for (int off = 16; off; off >>= 1) {
                double ov = __shfl_down_sync(0xffffffffu, myval, off);
                int    oi = __shfl_down_sync(0xffffffffu, myidx, off);
                if (ov < myval || (ov == myval && oi < myidx)) { myval = ov; myidx = oi; }
            }
            if ((tid & 31) == 0) { sh_wv[tid >> 5] = myval; sh_wi[tid >> 5] = myidx; }
            __syncthreads();

            if (tid == 0) {
                double bv = sh_wv[0]; int bi = sh_wi[0];
                #pragma unroll
                for (int w = 1; w < NWARPS; w++) {
                    if (sh_wv[w] < bv || (sh_wv[w] == bv && sh_wi[w] < bi)) { bv = sh_wv[w]; bi = sh_wi[w]; }
                }
                sh_SR[sh_SRlen++] = i;
                sh_minVal = bv;
                sh_SC[bi] = 1;
                int r = sh_row4col[bi];
                if (r < 0) sh_sink = bi; else sh_i = r;
            }
            __syncthreads();
            if (sh_sink >= 0) break;
        }

        // dual updates
        double minVal = sh_minVal;
        if (tid == 0) sh_u[cur] += minVal;
        int SRlen = sh_SRlen;
        for (int t = tid; t < SRlen; t += NTHREADS) {
            int r = sh_SR[t];
            if (r != cur) sh_u[r] += minVal - sh_shortest[sh_col4row[r]];
        }
        for (int j = tid; j < S_MAX; j += NTHREADS) {
            if (sh_SC[j]) sh_v[j] -= minVal - sh_shortest[j];
        }
        __syncthreads();

        // augment (serial, thread 0)
        if (tid == 0) {
            int j = sh_sink;
            while (true) {
                int i2 = sh_path[j];
                sh_row4col[j] = i2;
                int nxt = sh_col4row[i2];
                sh_col4row[i2] = j;
                if (i2 == cur) break;
                j = nxt;
            }
        }
        __syncthreads();
    }

    // ---- Phase 3: target class per slot ----
    for (int k = tid; k < nv; k += NTHREADS)
        sh_tc[sh_col4row[k]] = sh_cls[k];
    __syncthreads();

    // ---- Phase 4: losses ----
    double ce_num = 0.0, ce_den = 0.0, csum = 0.0, wsum = 0.0;

    for (int s = tid; s < S_MAX; s += NTHREADS) {
        const float* lg = logits + ((size_t)b * S_MAX + s) * 3;
        float l0 = lg[0], l1 = lg[1], l2 = lg[2];
        float mx = fmaxf(l0, fmaxf(l1, l2));
        float lse = mx + logf(expf(l0 - mx) + expf(l1 - mx) + expf(l2 - mx));
        int c = sh_tc[s];
        float lt = (c == 0) ? l0 : ((c == 1) ? l1 : l2);
        float nll = lse - lt;
        float w = (c == 0) ? 0.1f : 1.0f;
        ce_num += (double)(w * nll);
        ce_den += (double)w;
    }
    for (int k = tid; k < nv; k += NTHREADS) {
        const float* sp = strokes + ((size_t)b * S_MAX + sh_col4row[k]) * 10;
        const float* tp = tparams + ((size_t)b * G_MAX + sh_valid[k]) * 10;
        #pragma unroll
        for (int d8 = 0; d8 < 8; d8++) {
            float ad = fabsf(sp[d8] - tp[d8]);
            float sl = (ad < 0.1f) ? (0.5f * ad * ad / 0.1f) : (ad - 0.05f);
            csum += (double)ad + (double)sl;
        }
        wsum += (double)fabsf(sp[8] - tp[8]) + (double)fabsf(sp[9] - tp[9]);
    }

    // deterministic block reduction (warp shuffle + warp0 serial)
    double vals[4] = { ce_num, ce_den, csum, wsum };
    #pragma unroll
    for (int q = 0; q < 4; q++) {
        double v = vals[q];
        #pragma unroll
        for (int off = 16; off; off >>= 1)
            v += __shfl_down_sync(0xffffffffu, v, off);
        if ((tid & 31) == 0) sh_acc[tid >> 5] = v;
        __syncthreads();
        if (tid == 0) {
            double s = 0.0;
            #pragma unroll
            for (int w = 0; w < NWARPS; w++) s += sh_acc[w];
            g_part[b * 5 + q] = s;
        }
        __syncthreads();
    }
    if (tid == 0) g_part[b * 5 + 4] = (double)nv;
}

__global__ void finalize_kernel(float* out, int B)
{
    double ce_num = 0.0, ce_den = 0.0, csum = 0.0, wsum = 0.0, nm = 0.0;
    for (int b = 0; b < B; b++) {
        ce_num += g_part[b * 5 + 0];
        ce_den += g_part[b * 5 + 1];
        csum   += g_part[b * 5 + 2];
        wsum   += g_part[b * 5 + 3];
        nm     += g_part[b * 5 + 4];
    }
    double denom = nm > 1.0 ? nm : 1.0;
    double loss = CLASS_W * (ce_num / ce_den)
                + COORD_W * (csum / denom)
                + WIDTH_W * (wsum / denom);
    out[0] = (float)loss;
}

extern "C" void kernel_launch(void* const* d_in, const int* in_sizes, int n_in,
                              void* d_out, int out_size)
{
    const float* strokes = (const float*)d_in[0];
    const float* logits  = (const float*)d_in[1];
    const float* tparams = (const float*)d_in[2];
    const int*   tlabels = (const int*)d_in[3];

    int B = in_sizes[3] / G_MAX;
    if (B > B_MAX) B = B_MAX;

    detr_batch_kernel<<<B, NTHREADS>>>(strokes, logits, tparams, tlabels);
    finalize_kernel<<<1, 1>>>((float*)d_out, B);
}

// round 2
// speedup vs baseline: 1.5947x; 1.5947x over previous
#include <cuda_runtime.h>
#include <math.h>

// Problem constants (fixed by setup_inputs: B=128, S=300, G=100)
#define S_DIM 300
#define G_DIM 100
#define B_MAX 128
#define NTHREADS 320
#define NWARPS (NTHREADS / 32)
#define KSLOTS 10                 // ceil(300/32) columns per lane

#define CLASS_W 1.0
#define COORD_W 5.0
#define WIDTH_W 2.0
#define P0_W    2.0

static __device__ double g_part[B_MAX * 5];   // per-batch partials

// monotone map: float -> u32 preserving order (works for any sign)
__device__ __forceinline__ unsigned fmap(float f) {
    unsigned b = __float_as_uint(f);
    return (b & 0x80000000u) ? ~b : (b | 0x80000000u);
}
__device__ __forceinline__ float funmap(unsigned m) {
    return (m & 0x80000000u) ? __uint_as_float(m & 0x7fffffffu)
                             : __uint_as_float(~m);
}

extern __shared__ float s_C[];    // [G_DIM * S_DIM] f32 cost matrix (120 KB)

__global__ __launch_bounds__(NTHREADS, 1)
void detr_batch_kernel(const float* __restrict__ strokes,
                       const float* __restrict__ logits,
                       const float* __restrict__ tparams,
                       const int*   __restrict__ tlabels)
{
    const int b   = blockIdx.x;
    const int tid = threadIdx.x;

    __shared__ float  sh_u[G_DIM];
    __shared__ int    sh_row4col[S_DIM];
    __shared__ int    sh_col4row[G_DIM];
    __shared__ int    sh_path[S_DIM];
    __shared__ int    sh_SR[G_DIM + 4];
    __shared__ float  sh_minStep[G_DIM + 4];
    __shared__ int    sh_valid[G_DIM];
    __shared__ int    sh_cls[G_DIM];
    __shared__ float  sh_prob[S_DIM * 3];
    __shared__ int    sh_tc[S_DIM];
    __shared__ int    sh_nv;
    __shared__ double sh_acc[NWARPS];

    // ---- Phase 0: valid target compaction (order-preserving, warp 0) ----
    if (tid < 32) {
        int base = 0;
        #pragma unroll
        for (int c = 0; c < 4; c++) {
            int g = c * 32 + tid;
            int l = (g < G_DIM) ? tlabels[(size_t)b * G_DIM + g] : 0;
            unsigned bal = __ballot_sync(0xffffffffu, l > 0);
            if (l > 0) {
                int rank = base + __popc(bal & ((1u << tid) - 1u));
                sh_valid[rank] = g;
                sh_cls[rank]   = l;
            }
            base += __popc(bal);
        }
        if (tid == 0) sh_nv = base;
    }
    for (int j = tid; j < S_DIM; j += NTHREADS) {
        sh_tc[j] = 0;
        sh_row4col[j] = -1;
    }
    for (int i = tid; i < G_DIM; i += NTHREADS) {
        sh_u[i] = 0.0f;
        sh_col4row[i] = -1;
    }

    // ---- Phase 1a: softmax probs (f32, matches jax) ----
    for (int j = tid; j < S_DIM; j += NTHREADS) {
        const float* lg = logits + ((size_t)b * S_DIM + j) * 3;
        float l0 = lg[0], l1 = lg[1], l2 = lg[2];
        float mx = fmaxf(l0, fmaxf(l1, l2));
        float e0 = expf(l0 - mx), e1 = expf(l1 - mx), e2 = expf(l2 - mx);
        float s = e0 + e1 + e2;
        sh_prob[j * 3 + 0] = e0 / s;
        sh_prob[j * 3 + 1] = e1 / s;
        sh_prob[j * 3 + 2] = e2 / s;
    }
    __syncthreads();

    const int nv = sh_nv;

    // ---- Phase 1b: cost matrix into shared memory (f32) ----
    for (int idx = tid; idx < nv * S_DIM; idx += NTHREADS) {
        int i = idx / S_DIM;
        int j = idx - i * S_DIM;
        const float* sp = strokes + ((size_t)b * S_DIM + j) * 10;
        const float* tp = tparams + ((size_t)b * G_DIM + sh_valid[i]) * 10;
        float sum8 = 0.0f;
        #pragma unroll
        for (int k = 0; k < 8; k++)
            sum8 += fabsf(sp[k] - tp[k]);
        float wsum = fabsf(sp[8] - tp[8]) + fabsf(sp[9] - tp[9]);
        float p0   = fabsf(sp[0] - tp[0]) + fabsf(sp[1] - tp[1]);
        float cc   = -sh_prob[j * 3 + sh_cls[i]];
        s_C[i * S_DIM + j] = (float)CLASS_W * cc + (float)COORD_W * sum8
                           + (float)WIDTH_W * wsum + (float)P0_W * p0;
    }
    __syncthreads();

    // ---- Phase 2: Jonker-Volgenant LAP — single warp, no block barriers ----
    if (tid < 32) {
        const int lane = tid;
        float v_[KSLOTS];
        #pragma unroll
        for (int k = 0; k < KSLOTS; k++) v_[k] = 0.0f;

        for (int cur = 0; cur < nv; cur++) {
            float shortest[KSLOTS];
            unsigned scmask = 0;
            #pragma unroll
            for (int k = 0; k < KSLOTS; k++) shortest[k] = 3.0e38f;

            int   i      = cur;
            float minVal = 0.0f;
            int   t      = 0;
            int   sink   = -1;

            while (true) {
                if (lane == 0) sh_SR[t] = i;
                float base = minVal - sh_u[i];
                const float* Crow = s_C + i * S_DIM;

                unsigned bestm = 0xFFFFFFFFu;
                int      bestc = 0x7FFFFFFF;
                #pragma unroll
                for (int k = 0; k < KSLOTS; k++) {
                    int col = lane + 32 * k;
                    if (col < S_DIM && !((scmask >> k) & 1u)) {
                        float d = base + Crow[col] - v_[k];
                        if (d < shortest[k]) { shortest[k] = d; sh_path[col] = i; }
                        unsigned m = fmap(shortest[k]);
                        if (m < bestm) { bestm = m; bestc = col; }
                    }
                }
                unsigned gm = __reduce_min_sync(0xffffffffu, bestm);
                unsigned cc = (bestm == gm) ? (unsigned)bestc : 0xFFFFFFFFu;
                unsigned js = __reduce_min_sync(0xffffffffu, cc);

                minVal = funmap(gm);
                if (lane == 0) sh_minStep[t] = minVal;
                if (lane == (int)(js & 31u)) scmask |= 1u << (js >> 5);
                t++;

                int r = sh_row4col[js];
                if (r < 0) { sink = (int)js; break; }
                i = r;
            }
            __syncwarp();

            // dual updates
            if (lane == 0) sh_u[cur] += minVal;
            for (int s2 = 1 + lane; s2 < t; s2 += 32)
                sh_u[sh_SR[s2]] += minVal - sh_minStep[s2 - 1];
            #pragma unroll
            for (int k = 0; k < KSLOTS; k++)
                if ((scmask >> k) & 1u) v_[k] -= minVal - shortest[k];
            __syncwarp();

            // augment (lockstep, identical writes)
            {
                int j = sink;
                while (true) {
                    int i2 = sh_path[j];
                    sh_row4col[j] = i2;
                    int nxt = sh_col4row[i2];
                    sh_col4row[i2] = j;
                    if (i2 == cur) break;
                    j = nxt;
                }
            }
            __syncwarp();
        }
    }
    __syncthreads();

    // ---- Phase 3: target class per slot ----
    for (int k = tid; k < nv; k += NTHREADS)
        sh_tc[sh_col4row[k]] = sh_cls[k];
    __syncthreads();

    // ---- Phase 4: losses (f32 elementwise, f64 accumulate) ----
    double ce_num = 0.0, ce_den = 0.0, csum = 0.0, wsum = 0.0;

    for (int s = tid; s < S_DIM; s += NTHREADS) {
        int c = sh_tc[s];
        float nll = -logf(sh_prob[s * 3 + c]);
        float w = (c == 0) ? 0.1f : 1.0f;
        ce_num += (double)(w * nll);
        ce_den += (double)w;
    }
    for (int k = tid; k < nv; k += NTHREADS) {
        const float* sp = strokes + ((size_t)b * S_DIM + sh_col4row[k]) * 10;
        const float* tp = tparams + ((size_t)b * G_DIM + sh_valid[k]) * 10;
        #pragma unroll
        for (int d8 = 0; d8 < 8; d8++) {
            float ad = fabsf(sp[d8] - tp[d8]);
            float sl = (ad < 0.1f) ? (0.5f * ad * ad / 0.1f) : (ad - 0.05f);
            csum += (double)ad + (double)sl;
        }
        wsum += (double)fabsf(sp[8] - tp[8]) + (double)fabsf(sp[9] - tp[9]);
    }

    double vals[4] = { ce_num, ce_den, csum, wsum };
    #pragma unroll
    for (int q = 0; q < 4; q++) {
        double v = vals[q];
        #pragma unroll
        for (int off = 16; off; off >>= 1)
            v += __shfl_down_sync(0xffffffffu, v, off);
        if ((tid & 31) == 0) sh_acc[tid >> 5] = v;
        __syncthreads();
        if (tid == 0) {
            double s = 0.0;
            #pragma unroll
            for (int w = 0; w < NWARPS; w++) s += sh_acc[w];
            g_part[b * 5 + q] = s;
        }
        __syncthreads();
    }
    if (tid == 0) g_part[b * 5 + 4] = (double)nv;
}

__global__ void finalize_kernel(float* out, int B)
{
    int lane = threadIdx.x;
    double a0 = 0.0, a1 = 0.0, a2 = 0.0, a3 = 0.0, a4 = 0.0;
    for (int b = lane; b < B; b += 32) {
        a0 += g_part[b * 5 + 0];
        a1 += g_part[b * 5 + 1];
        a2 += g_part[b * 5 + 2];
        a3 += g_part[b * 5 + 3];
        a4 += g_part[b * 5 + 4];
    }
    #pragma unroll
    for (int off = 16; off; off >>= 1) {
        a0 += __shfl_down_sync(0xffffffffu, a0, off);
        a1 += __shfl_down_sync(0xffffffffu, a1, off);
        a2 += __shfl_down_sync(0xffffffffu, a2, off);
        a3 += __shfl_down_sync(0xffffffffu, a3, off);
        a4 += __shfl_down_sync(0xffffffffu, a4, off);
    }
    if (lane == 0) {
        double denom = a4 > 1.0 ? a4 : 1.0;
        double loss = CLASS_W * (a0 / a1)
                    + COORD_W * (a2 / denom)
                    + WIDTH_W * (a3 / denom);
        out[0] = (float)loss;
    }
}

extern "C" void kernel_launch(void* const* d_in, const int* in_sizes, int n_in,
                              void* d_out, int out_size)
{
    const float* strokes = (const float*)d_in[0];
    const float* logits  = (const float*)d_in[1];
    const float* tparams = (const float*)d_in[2];
    const int*   tlabels = (const int*)d_in[3];

    int B = in_sizes[3] / G_DIM;
    if (B > B_MAX) B = B_MAX;

    const int dyn_smem = G_DIM * S_DIM * (int)sizeof(float);   // 120000 B
    cudaFuncSetAttribute(detr_batch_kernel,
                         cudaFuncAttributeMaxDynamicSharedMemorySize, dyn_smem);

    detr_batch_kernel<<<B, NTHREADS, dyn_smem>>>(strokes, logits, tparams, tlabels);
    finalize_kernel<<<1, 32>>>((float*)d_out, B);
}

// round 3
// speedup vs baseline: 3.0818x; 1.9325x over previous
#include <cuda_runtime.h>
#include <math.h>

// Problem constants (fixed by setup_inputs: B=128, S=300, G=100)
#define S_DIM 300
#define SPAD  320                 // padded column count (removes bounds checks)
#define G_DIM 100
#define B_MAX 128
#define NTHREADS 320
#define NWARPS (NTHREADS / 32)
#define KSLOTS 10                 // 320/32 columns per lane
#define BIGC  1.0e30f

#define CLASS_W 1.0
#define COORD_W 5.0
#define WIDTH_W 2.0
#define P0_W    2.0

static __device__ double g_part[B_MAX * 5];   // per-batch partials

// monotone map: float -> u32 preserving order
__device__ __forceinline__ unsigned fmap(float f) {
    unsigned b = __float_as_uint(f);
    return (b & 0x80000000u) ? ~b : (b | 0x80000000u);
}
__device__ __forceinline__ float funmap(unsigned m) {
    return (m & 0x80000000u) ? __uint_as_float(m & 0x7fffffffu)
                             : __uint_as_float(~m);
}

extern __shared__ float s_C[];    // [G_DIM * SPAD] f32 cost matrix (128 KB)

__global__ __launch_bounds__(NTHREADS, 1)
void detr_batch_kernel(const float* __restrict__ strokes,
                       const float* __restrict__ logits,
                       const float* __restrict__ tparams,
                       const int*   __restrict__ tlabels)
{
    const int b   = blockIdx.x;
    const int tid = threadIdx.x;
    const int wid = tid >> 5;
    const int lane = tid & 31;

    __shared__ float  sh_strokes[S_DIM * 10];
    __shared__ float  sh_tpv[G_DIM * 10];
    __shared__ float  sh_prob[S_DIM * 3];
    __shared__ float  sh_nll[S_DIM * 3];
    __shared__ float  sh_u[G_DIM];
    __shared__ float  sh_minStep[G_DIM + 4];
    __shared__ int    sh_row4col[SPAD];
    __shared__ int    sh_col4row[G_DIM];
    __shared__ int    sh_path[SPAD];
    __shared__ int    sh_SR[G_DIM + 4];
    __shared__ int    sh_valid[G_DIM];
    __shared__ int    sh_cls[G_DIM];
    __shared__ int    sh_cand[G_DIM];
    __shared__ int    sh_free[G_DIM];
    __shared__ int    sh_tc[S_DIM];
    __shared__ int    sh_nv;
    __shared__ double sh_acc[NWARPS];

    // ---- Phase 0: valid target compaction (order-preserving, warp 0) ----
    if (tid < 32) {
        int base = 0;
        #pragma unroll
        for (int c = 0; c < 4; c++) {
            int g = c * 32 + tid;
            int l = (g < G_DIM) ? tlabels[(size_t)b * G_DIM + g] : 0;
            unsigned bal = __ballot_sync(0xffffffffu, l > 0);
            if (l > 0) {
                int rank = base + __popc(bal & ((1u << tid) - 1u));
                sh_valid[rank] = g;
                sh_cls[rank]   = l;
            }
            base += __popc(bal);
        }
        if (tid == 0) sh_nv = base;
    }
    for (int j = tid; j < S_DIM; j += NTHREADS) sh_tc[j] = 0;
    for (int j = tid; j < SPAD; j += NTHREADS)  sh_row4col[j] = -1;
    for (int i = tid; i < G_DIM; i += NTHREADS) sh_col4row[i] = -1;

    // stage strokes into smem
    for (int k = tid; k < S_DIM * 10; k += NTHREADS)
        sh_strokes[k] = strokes[(size_t)b * S_DIM * 10 + k];

    // ---- Phase 1a: softmax probs (f32, matches jax) ----
    for (int j = tid; j < S_DIM; j += NTHREADS) {
        const float* lg = logits + ((size_t)b * S_DIM + j) * 3;
        float l0 = lg[0], l1 = lg[1], l2 = lg[2];
        float mx = fmaxf(l0, fmaxf(l1, l2));
        float e0 = expf(l0 - mx), e1 = expf(l1 - mx), e2 = expf(l2 - mx);
        float s = e0 + e1 + e2;
        sh_prob[j * 3 + 0] = e0 / s;
        sh_prob[j * 3 + 1] = e1 / s;
        sh_prob[j * 3 + 2] = e2 / s;
    }
    __syncthreads();

    const int nv = sh_nv;

    // stage valid target params (gather)
    for (int k = tid; k < nv * 10; k += NTHREADS) {
        int i = k / 10, d = k - i * 10;
        sh_tpv[k] = tparams[((size_t)b * G_DIM + sh_valid[i]) * 10 + d];
    }
    __syncthreads();

    // ---- Phase 1b: cost matrix into shared memory (f32), padded cols ----
    for (int idx = tid; idx < nv * S_DIM; idx += NTHREADS) {
        int i = idx / S_DIM;
        int j = idx - i * S_DIM;
        const float* sp = sh_strokes + j * 10;
        const float* tp = sh_tpv + i * 10;
        float sum8 = 0.0f;
        #pragma unroll
        for (int k = 0; k < 8; k++)
            sum8 += fabsf(sp[k] - tp[k]);
        float wsum = fabsf(sp[8] - tp[8]) + fabsf(sp[9] - tp[9]);
        float p0   = fabsf(sp[0] - tp[0]) + fabsf(sp[1] - tp[1]);
        float cc   = -sh_prob[j * 3 + sh_cls[i]];
        s_C[i * SPAD + j] = (float)CLASS_W * cc + (float)COORD_W * sum8
                          + (float)WIDTH_W * wsum + (float)P0_W * p0;
    }
    // pad columns with a huge sentinel
    for (int idx = tid; idx < nv * (SPAD - S_DIM); idx += NTHREADS) {
        int i = idx / (SPAD - S_DIM);
        int p = idx - i * (SPAD - S_DIM);
        s_C[i * SPAD + S_DIM + p] = BIGC;
    }
    __syncthreads();

    // ---- Phase 1c: row minima (all warps) -> feasible duals + greedy cands ----
    for (int row = wid; row < nv; row += NWARPS) {
        const float* Crow = s_C + row * SPAD;
        float bm = 3.0e38f; int bc = 0;
        #pragma unroll
        for (int k = 0; k < KSLOTS; k++) {
            float c = Crow[lane + 32 * k];
            if (c < bm) { bm = c; bc = lane + 32 * k; }
        }
        unsigned m = fmap(bm);
        unsigned g = __reduce_min_sync(0xffffffffu, m);
        unsigned sel = (m == g) ? (unsigned)bc : 0xFFFFFFFFu;
        unsigned jm = __reduce_min_sync(0xffffffffu, sel);
        if (lane == 0) { sh_u[row] = funmap(g); sh_cand[row] = (int)jm; }
    }
    __syncthreads();

    // ---- Phase 2: LAPJV — warp 0: greedy seed + Dijkstra augmentations ----
    // ---- meanwhile warps 1..9 precompute NLL table for the CE loss     ----
    if (tid < 32) {
        float v_[KSLOTS];
        #pragma unroll
        for (int k = 0; k < KSLOTS; k++) v_[k] = 0.0f;

        // greedy assignment (lockstep: all lanes do identical ops)
        int nf = 0;
        for (int i = 0; i < nv; i++) {
            int j = sh_cand[i];
            if (sh_row4col[j] < 0) { sh_row4col[j] = i; sh_col4row[i] = j; }
            else sh_free[nf++] = i;
        }
        __syncwarp();

        for (int f = 0; f < nf; f++) {
            const int cur = sh_free[f];
            float shortest[KSLOTS];
            unsigned scmask = 0;
            #pragma unroll
            for (int k = 0; k < KSLOTS; k++) shortest[k] = 3.0e38f;

            int   i      = cur;
            float minVal = 0.0f;
            int   t      = 0;
            int   sink   = -1;

            while (true) {
                if (lane == 0) sh_SR[t] = i;
                float base = minVal - sh_u[i];
                const float* Crow = s_C + i * SPAD;

                unsigned bestm = 0xFFFFFFFFu;
                int      bestc = 0x7FFFFFFF;
                #pragma unroll
                for (int k = 0; k < KSLOTS; k++) {
                    int col = lane + 32 * k;
                    if (!((scmask >> k) & 1u)) {
                        float d = base + Crow[col] - v_[k];
                        if (d < shortest[k]) { shortest[k] = d; sh_path[col] = i; }
                        unsigned m = fmap(shortest[k]);
                        if (m < bestm) { bestm = m; bestc = col; }
                    }
                }
                unsigned gm = __reduce_min_sync(0xffffffffu, bestm);
                unsigned cc = (bestm == gm) ? (unsigned)bestc : 0xFFFFFFFFu;
                unsigned js = __reduce_min_sync(0xffffffffu, cc);

                minVal = funmap(gm);
                if (lane == 0) sh_minStep[t] = minVal;
                if (lane == (int)(js & 31u)) scmask |= 1u << (js >> 5);
                t++;

                int r = sh_row4col[js];
                if (r < 0) { sink = (int)js; break; }
                i = r;
            }
            __syncwarp();

            // dual updates
            if (lane == 0) sh_u[cur] += minVal;
            for (int s2 = 1 + lane; s2 < t; s2 += 32)
                sh_u[sh_SR[s2]] += minVal - sh_minStep[s2 - 1];
            #pragma unroll
            for (int k = 0; k < KSLOTS; k++)
                if ((scmask >> k) & 1u) v_[k] -= minVal - shortest[k];
            __syncwarp();

            // augment (lockstep, identical writes)
            {
                int j = sink;
                while (true) {
                    int i2 = sh_path[j];
                    sh_row4col[j] = i2;
                    int nxt = sh_col4row[i2];
                    sh_col4row[i2] = j;
                    if (i2 == cur) break;
                    j = nxt;
                }
            }
            __syncwarp();
        }
    } else {
        // warps 1..9: NLL table (overlapped with LAP)
        for (int s = tid - 32; s < S_DIM; s += NTHREADS - 32) {
            sh_nll[s * 3 + 0] = -logf(sh_prob[s * 3 + 0]);
            sh_nll[s * 3 + 1] = -logf(sh_prob[s * 3 + 1]);
            sh_nll[s * 3 + 2] = -logf(sh_prob[s * 3 + 2]);
        }
    }
    __syncthreads();

    // ---- Phase 3: target class per slot ----
    for (int k = tid; k < nv; k += NTHREADS)
        sh_tc[sh_col4row[k]] = sh_cls[k];
    __syncthreads();

    // ---- Phase 4: losses (f32 elementwise, f64 accumulate) ----
    double ce_num = 0.0, ce_den = 0.0, csum = 0.0, wsum = 0.0;

    for (int s = tid; s < S_DIM; s += NTHREADS) {
        int c = sh_tc[s];
        float nll = sh_nll[s * 3 + c];
        float w = (c == 0) ? 0.1f : 1.0f;
        ce_num += (double)(w * nll);
        ce_den += (double)w;
    }
    for (int k = tid; k < nv; k += NTHREADS) {
        const float* sp = sh_strokes + sh_col4row[k] * 10;
        const float* tp = sh_tpv + k * 10;
        #pragma unroll
        for (int d8 = 0; d8 < 8; d8++) {
            float ad = fabsf(sp[d8] - tp[d8]);
            float sl = (ad < 0.1f) ? (0.5f * ad * ad / 0.1f) : (ad - 0.05f);
            csum += (double)ad + (double)sl;
        }
        wsum += (double)fabsf(sp[8] - tp[8]) + (double)fabsf(sp[9] - tp[9]);
    }

    double vals[4] = { ce_num, ce_den, csum, wsum };
    #pragma unroll
    for (int q = 0; q < 4; q++) {
        double v = vals[q];
        #pragma unroll
        for (int off = 16; off; off >>= 1)
            v += __shfl_down_sync(0xffffffffu, v, off);
        if (lane == 0) sh_acc[wid] = v;
        __syncthreads();
        if (tid == 0) {
            double s = 0.0;
            #pragma unroll
            for (int w = 0; w < NWARPS; w++) s += sh_acc[w];
            g_part[b * 5 + q] = s;
        }
        __syncthreads();
    }
    if (tid == 0) g_part[b * 5 + 4] = (double)nv;
}

__global__ void finalize_kernel(float* out, int B)
{
    int lane = threadIdx.x;
    double a0 = 0.0, a1 = 0.0, a2 = 0.0, a3 = 0.0, a4 = 0.0;
    for (int b = lane; b < B; b += 32) {
        a0 += g_part[b * 5 + 0];
        a1 += g_part[b * 5 + 1];
        a2 += g_part[b * 5 + 2];
        a3 += g_part[b * 5 + 3];
        a4 += g_part[b * 5 + 4];
    }
    #pragma unroll
    for (int off = 16; off; off >>= 1) {
        a0 += __shfl_down_sync(0xffffffffu, a0, off);
        a1 += __shfl_down_sync(0xffffffffu, a1, off);
        a2 += __shfl_down_sync(0xffffffffu, a2, off);
        a3 += __shfl_down_sync(0xffffffffu, a3, off);
        a4 += __shfl_down_sync(0xffffffffu, a4, off);
    }
    if (lane == 0) {
        double denom = a4 > 1.0 ? a4 : 1.0;
        double loss = CLASS_W * (a0 / a1)
                    + COORD_W * (a2 / denom)
                    + WIDTH_W * (a3 / denom);
        out[0] = (float)loss;
    }
}

extern "C" void kernel_launch(void* const* d_in, const int* in_sizes, int n_in,
                              void* d_out, int out_size)
{
    const float* strokes = (const float*)d_in[0];
    const float* logits  = (const float*)d_in[1];
    const float* tparams = (const float*)d_in[2];
    const int*   tlabels = (const int*)d_in[3];

    int B = in_sizes[3] / G_DIM;
    if (B > B_MAX) B = B_MAX;

    const int dyn_smem = G_DIM * SPAD * (int)sizeof(float);   // 128000 B
    cudaFuncSetAttribute(detr_batch_kernel,
                         cudaFuncAttributeMaxDynamicSharedMemorySize, dyn_smem);

    detr_batch_kernel<<<B, NTHREADS, dyn_smem>>>(strokes, logits, tparams, tlabels);
    finalize_kernel<<<1, 32>>>((float*)d_out, B);
}

// round 4
// speedup vs baseline: 3.5018x; 1.1363x over previous
#include <cuda_runtime.h>
#include <math.h>

// Problem constants (fixed by setup_inputs: B=128, S=300, G=100)
#define S_DIM 300
#define SPAD  320
#define G_DIM 100
#define B_MAX 128
#define NTHREADS 320
#define NWARPS (NTHREADS / 32)
#define KSLOTS 10
#define BIGC  1.0e30f

#define CLASS_W 1.0
#define COORD_W 5.0
#define WIDTH_W 2.0
#define P0_W    2.0

static __device__ double   g_part[B_MAX * 5];
static __device__ unsigned g_done = 0;

// monotone map: float -> u32 preserving order
__device__ __forceinline__ unsigned fmap(float f) {
    unsigned b = __float_as_uint(f);
    return (b & 0x80000000u) ? ~b : (b | 0x80000000u);
}
__device__ __forceinline__ float funmap(unsigned m) {
    return (m & 0x80000000u) ? __uint_as_float(m & 0x7fffffffu)
                             : __uint_as_float(~m);
}

extern __shared__ float s_C[];    // [G_DIM * SPAD] f32 cost matrix (128 KB)

__global__ __launch_bounds__(NTHREADS, 1)
void detr_batch_kernel(const float* __restrict__ strokes,
                       const float* __restrict__ logits,
                       const float* __restrict__ tparams,
                       const int*   __restrict__ tlabels,
                       float* __restrict__ out)
{
    const int b    = blockIdx.x;
    const int tid  = threadIdx.x;
    const int wid  = tid >> 5;
    const int lane = tid & 31;

    __shared__ float  sh_strokes[S_DIM * 10];
    __shared__ float  sh_tpv[G_DIM * 12];       // stride 12 for float4 loads
    __shared__ float  sh_nll[S_DIM * 3];
    __shared__ float  sh_u[G_DIM];
    __shared__ float  sh_minStep[G_DIM + 4];
    __shared__ int    sh_row4col[SPAD];
    __shared__ int    sh_col4row[G_DIM];
    __shared__ int    sh_path[SPAD];
    __shared__ int    sh_SR[G_DIM + 4];
    __shared__ int    sh_valid[G_DIM];
    __shared__ int    sh_cls[G_DIM];
    __shared__ int    sh_cand[G_DIM];
    __shared__ int    sh_free[G_DIM];
    __shared__ int    sh_owner[SPAD];
    __shared__ int    sh_tc[S_DIM];
    __shared__ int    sh_nv, sh_nf, sh_last;
    __shared__ double sh_acc[NWARPS];

    // ---- Phase 0 (warp 0): valid-target compaction; all threads: staging ----
    if (tid < 32) {
        int base = 0;
        #pragma unroll
        for (int c = 0; c < 4; c++) {
            int g = c * 32 + tid;
            int l = (g < G_DIM) ? tlabels[(size_t)b * G_DIM + g] : 0;
            unsigned bal = __ballot_sync(0xffffffffu, l > 0);
            if (l > 0) {
                int rank = base + __popc(bal & ((1u << tid) - 1u));
                sh_valid[rank] = g;
                sh_cls[rank]   = l;
            }
            base += __popc(bal);
        }
        if (tid == 0) sh_nv = base;
    }

    const int j = tid;                 // this thread's column
    const bool active = (j < S_DIM);

    // per-column data in registers
    float sp[10];
    float pc1 = 0.0f, pc2 = 0.0f;
    if (active) {
        const float* g = strokes + ((size_t)b * S_DIM + j) * 10;
        #pragma unroll
        for (int d = 0; d < 10; d++) { sp[d] = g[d]; sh_strokes[j * 10 + d] = sp[d]; }

        const float* lg = logits + ((size_t)b * S_DIM + j) * 3;
        float l0 = lg[0], l1 = lg[1], l2 = lg[2];
        float mx = fmaxf(l0, fmaxf(l1, l2));
        float e0 = expf(l0 - mx), e1 = expf(l1 - mx), e2 = expf(l2 - mx);
        float s  = e0 + e1 + e2;
        pc1 = -(e1 / s);
        pc2 = -(e2 / s);
        float lse = mx + logf(s);
        sh_nll[j * 3 + 0] = lse - l0;
        sh_nll[j * 3 + 1] = lse - l1;
        sh_nll[j * 3 + 2] = lse - l2;
    }
    for (int p = tid; p < S_DIM; p += NTHREADS) sh_tc[p] = 0;
    for (int p = tid; p < SPAD; p += NTHREADS)  { sh_row4col[p] = -1; sh_owner[p] = 0x7fffffff; }
    for (int p = tid; p < G_DIM; p += NTHREADS) sh_col4row[p] = -1;
    __syncthreads();

    const int nv = sh_nv;

    // ---- Phase 1: gather valid target params (stride 12) ----
    for (int k = tid; k < nv * 10; k += NTHREADS) {
        int i = k / 10, d = k - i * 10;
        sh_tpv[i * 12 + d] = tparams[((size_t)b * G_DIM + sh_valid[i]) * 10 + d];
    }
    __syncthreads();

    // ---- Phase 2: cost build, column-per-thread ----
    {
        for (int i = 0; i < nv; i++) {
            float4 t0 = *(const float4*)&sh_tpv[i * 12 + 0];
            float4 t1 = *(const float4*)&sh_tpv[i * 12 + 4];
            float  t8 = sh_tpv[i * 12 + 8];
            float  t9 = sh_tpv[i * 12 + 9];
            float acc;
            if (active) {
                acc = (sh_cls[i] == 1) ? pc1 : pc2;
                acc += 7.0f * fabsf(sp[0] - t0.x);
                acc += 7.0f * fabsf(sp[1] - t0.y);
                acc += 5.0f * fabsf(sp[2] - t0.z);
                acc += 5.0f * fabsf(sp[3] - t0.w);
                acc += 5.0f * fabsf(sp[4] - t1.x);
                acc += 5.0f * fabsf(sp[5] - t1.y);
                acc += 5.0f * fabsf(sp[6] - t1.z);
                acc += 5.0f * fabsf(sp[7] - t1.w);
                acc += 2.0f * fabsf(sp[8] - t8);
                acc += 2.0f * fabsf(sp[9] - t9);
            } else {
                acc = BIGC;
            }
            s_C[i * SPAD + j] = acc;
        }
    }
    __syncthreads();

    // ---- Phase 3: row minima (warp per row) -> duals u + greedy candidates ----
    for (int row = wid; row < nv; row += NWARPS) {
        const float* Crow = s_C + row * SPAD;
        float bm = 3.0e38f; int bc = 0;
        #pragma unroll
        for (int k = 0; k < KSLOTS; k++) {
            float c = Crow[lane + 32 * k];
            if (c < bm) { bm = c; bc = lane + 32 * k; }
        }
        unsigned m = fmap(bm);
        unsigned g = __reduce_min_sync(0xffffffffu, m);
        unsigned sel = (m == g) ? (unsigned)bc : 0xFFFFFFFFu;
        unsigned jm = __reduce_min_sync(0xffffffffu, sel);
        if (lane == 0) { sh_u[row] = funmap(g); sh_cand[row] = (int)jm; }
    }
    __syncthreads();

    // ---- Phase 4a: parallel greedy conflict resolution (winner = min row) ----
    for (int i = tid; i < nv; i += NTHREADS)
        atomicMin_block(&sh_owner[sh_cand[i]], i);
    __syncthreads();

    if (tid < 32) {
        int base = 0;
        #pragma unroll
        for (int c = 0; c < 4; c++) {
            int i = c * 32 + tid;
            bool isfree = false;
            if (i < nv) {
                int cj = sh_cand[i];
                if (sh_owner[cj] == i) { sh_col4row[i] = cj; sh_row4col[cj] = i; }
                else isfree = true;
            }
            unsigned bal = __ballot_sync(0xffffffffu, isfree);
            if (isfree) {
                int rank = base + __popc(bal & ((1u << tid) - 1u));
                sh_free[rank] = i;
            }
            base += __popc(bal);
        }
        if (tid == 0) sh_nf = base;
    }
    __syncthreads();

    // ---- Phase 4b: Dijkstra augmentations for the free rows (warp 0) ----
    if (tid < 32) {
        const int nf = sh_nf;
        float v_[KSLOTS];
        #pragma unroll
        for (int k = 0; k < KSLOTS; k++) v_[k] = 0.0f;

        for (int f = 0; f < nf; f++) {
            const int cur = sh_free[f];
            float shortest[KSLOTS];
            unsigned scmask = 0;
            #pragma unroll
            for (int k = 0; k < KSLOTS; k++) shortest[k] = 3.0e38f;

            int   i      = cur;
            float minVal = 0.0f;
            int   t      = 0;
            int   sink   = -1;

            while (true) {
                if (lane == 0) sh_SR[t] = i;
                float base = minVal - sh_u[i];
                const float* Crow = s_C + i * SPAD;

                unsigned bestm = 0xFFFFFFFFu;
                int      bestc = 0x7FFFFFFF;
                #pragma unroll
                for (int k = 0; k < KSLOTS; k++) {
                    int col = lane + 32 * k;
                    if (!((scmask >> k) & 1u)) {
                        float d = base + Crow[col] - v_[k];
                        if (d < shortest[k]) { shortest[k] = d; sh_path[col] = i; }
                        unsigned m = fmap(shortest[k]);
                        if (m < bestm) { bestm = m; bestc = col; }
                    }
                }
                unsigned gm = __reduce_min_sync(0xffffffffu, bestm);
                unsigned cc = (bestm == gm) ? (unsigned)bestc : 0xFFFFFFFFu;
                unsigned js = __reduce_min_sync(0xffffffffu, cc);

                minVal = funmap(gm);
                if (lane == 0) sh_minStep[t] = minVal;
                if (lane == (int)(js & 31u)) scmask |= 1u << (js >> 5);
                t++;

                int r = sh_row4col[js];
                if (r < 0) { sink = (int)js; break; }
                i = r;
            }
            __syncwarp();

            if (lane == 0) sh_u[cur] += minVal;
            for (int s2 = 1 + lane; s2 < t; s2 += 32)
                sh_u[sh_SR[s2]] += minVal - sh_minStep[s2 - 1];
            #pragma unroll
            for (int k = 0; k < KSLOTS; k++)
                if ((scmask >> k) & 1u) v_[k] -= minVal - shortest[k];
            __syncwarp();

            {
                int jj = sink;
                while (true) {
                    int i2 = sh_path[jj];
                    sh_row4col[jj] = i2;
                    int nxt = sh_col4row[i2];
                    sh_col4row[i2] = jj;
                    if (i2 == cur) break;
                    jj = nxt;
                }
            }
            __syncwarp();
        }
    }
    __syncthreads();

    // ---- Phase 5: target class per slot ----
    for (int k = tid; k < nv; k += NTHREADS)
        sh_tc[sh_col4row[k]] = sh_cls[k];
    __syncthreads();

    // ---- Phase 6: losses (f32 elementwise, f64 accumulate) ----
    double ce_num = 0.0, ce_den = 0.0, csum = 0.0, wsum = 0.0;

    for (int s = tid; s < S_DIM; s += NTHREADS) {
        int c = sh_tc[s];
        float nll = sh_nll[s * 3 + c];
        float w = (c == 0) ? 0.1f : 1.0f;
        ce_num += (double)(w * nll);
        ce_den += (double)w;
    }
    for (int k = tid; k < nv; k += NTHREADS) {
        const float* spv = sh_strokes + sh_col4row[k] * 10;
        const float* tp  = sh_tpv + k * 12;
        #pragma unroll
        for (int d8 = 0; d8 < 8; d8++) {
            float ad = fabsf(spv[d8] - tp[d8]);
            float sl = (ad < 0.1f) ? (0.5f * ad * ad / 0.1f) : (ad - 0.05f);
            csum += (double)ad + (double)sl;
        }
        wsum += (double)fabsf(spv[8] - tp[8]) + (double)fabsf(spv[9] - tp[9]);
    }

    double vals[4] = { ce_num, ce_den, csum, wsum };
    #pragma unroll
    for (int q = 0; q < 4; q++) {
        double v = vals[q];
        #pragma unroll
        for (int off = 16; off; off >>= 1)
            v += __shfl_down_sync(0xffffffffu, v, off);
        if (lane == 0) sh_acc[wid] = v;
        __syncthreads();
        if (tid == 0) {
            double s = 0.0;
            #pragma unroll
            for (int w = 0; w < NWARPS; w++) s += sh_acc[w];
            g_part[b * 5 + q] = s;
        }
        __syncthreads();
    }

    // ---- Phase 7: fused finalize (last block) ----
    if (tid == 0) {
        g_part[b * 5 + 4] = (double)nv;
        __threadfence();
        unsigned old = atomicInc(&g_done, gridDim.x - 1);
        sh_last = (old == gridDim.x - 1) ? 1 : 0;
    }
    __syncthreads();

    if (sh_last && tid < 32) {
        __threadfence();
        const volatile double* gp = g_part;
        double a0 = 0.0, a1 = 0.0, a2 = 0.0, a3 = 0.0, a4 = 0.0;
        for (int bb = lane; bb < (int)gridDim.x; bb += 32) {
            a0 += gp[bb * 5 + 0];
            a1 += gp[bb * 5 + 1];
            a2 += gp[bb * 5 + 2];
            a3 += gp[bb * 5 + 3];
            a4 += gp[bb * 5 + 4];
        }
        #pragma unroll
        for (int off = 16; off; off >>= 1) {
            a0 += __shfl_down_sync(0xffffffffu, a0, off);
            a1 += __shfl_down_sync(0xffffffffu, a1, off);
            a2 += __shfl_down_sync(0xffffffffu, a2, off);
            a3 += __shfl_down_sync(0xffffffffu, a3, off);
            a4 += __shfl_down_sync(0xffffffffu, a4, off);
        }
        if (lane == 0) {
            double denom = a4 > 1.0 ? a4 : 1.0;
            double loss = CLASS_W * (a0 / a1)
                        + COORD_W * (a2 / denom)
                        + WIDTH_W * (a3 / denom);
            out[0] = (float)loss;
        }
    }
}

extern "C" void kernel_launch(void* const* d_in, const int* in_sizes, int n_in,
                              void* d_out, int out_size)
{
    const float* strokes = (const float*)d_in[0];
    const float* logits  = (const float*)d_in[1];
    const float* tparams = (const float*)d_in[2];
    const int*   tlabels = (const int*)d_in[3];

    int B = in_sizes[3] / G_DIM;
    if (B > B_MAX) B = B_MAX;

    const int dyn_smem = G_DIM * SPAD * (int)sizeof(float);   // 128000 B
    cudaFuncSetAttribute(detr_batch_kernel,
                         cudaFuncAttributeMaxDynamicSharedMemorySize, dyn_smem);

    detr_batch_kernel<<<B, NTHREADS, dyn_smem>>>(strokes, logits, tparams, tlabels,
                                                 (float*)d_out);
}

// round 6
// speedup vs baseline: 3.8130x; 1.0889x over previous
#include <cuda_runtime.h>
#include <math.h>

// Problem constants (fixed by setup_inputs: B=128, S=300, G=100)
#define S_DIM 300
#define SPAD  320
#define G_DIM 100
#define B_MAX 128
#define NTHREADS 320
#define NWARPS (NTHREADS / 32)
#define KSLOTS 10
#define BIGC  1.0e30f

#define CLASS_W 1.0
#define COORD_W 5.0
#define WIDTH_W 2.0
#define P0_W    2.0

static __device__ double   g_part[B_MAX * 5];
static __device__ unsigned g_done = 0;

// All costs carry a +1.0f offset so every entry is >= 0. For non-negative
// IEEE floats, raw bit patterns are order-isomorphic to values, so argmin
// keys are plain __float_as_uint(x).

extern __shared__ float s_C[];    // [G_DIM * SPAD] f32 cost matrix (128 KB)

// pairwise merge preferring LEFT on ties (left = smaller column)
__device__ __forceinline__ void kmerge(unsigned& kL, int& cL, unsigned kR, int cR) {
    if (kR < kL) { kL = kR; cL = cR; }
}

__global__ __launch_bounds__(NTHREADS, 1)
void detr_batch_kernel(const float* __restrict__ strokes,
                       const float* __restrict__ logits,
                       const float* __restrict__ tparams,
                       const int*   __restrict__ tlabels,
                       float* __restrict__ out)
{
    const int b    = blockIdx.x;
    const int tid  = threadIdx.x;
    const int wid  = tid >> 5;
    const int lane = tid & 31;

    __shared__ float  sh_strokes[S_DIM * 10];
    __shared__ float  sh_tpv[G_DIM * 12];
    __shared__ float  sh_nll[S_DIM * 3];
    __shared__ float  sh_u[G_DIM];
    __shared__ float  sh_minStep[G_DIM + 4];
    __shared__ int    sh_row4col[SPAD];
    __shared__ int    sh_col4row[G_DIM];
    __shared__ int    sh_path[SPAD];
    __shared__ int    sh_SR[G_DIM + 4];
    __shared__ int    sh_valid[G_DIM];
    __shared__ int    sh_cls[G_DIM];
    __shared__ int    sh_cand[G_DIM];
    __shared__ int    sh_free[G_DIM];
    __shared__ int    sh_owner[SPAD];
    __shared__ int    sh_tc[S_DIM];
    __shared__ int    sh_nv, sh_nf, sh_last;
    __shared__ double sh_acc[NWARPS * 4];

    // ---- Phase 0 (warp 0): valid-target compaction; all: staging ----
    if (tid < 32) {
        int base = 0;
        #pragma unroll
        for (int c = 0; c < 4; c++) {
            int g = c * 32 + tid;
            int l = (g < G_DIM) ? tlabels[(size_t)b * G_DIM + g] : 0;
            unsigned bal = __ballot_sync(0xffffffffu, l > 0);
            if (l > 0) {
                int rank = base + __popc(bal & ((1u << tid) - 1u));
                sh_valid[rank] = g;
                sh_cls[rank]   = l;
            }
            base += __popc(bal);
        }
        if (tid == 0) sh_nv = base;
    }

    const int j = tid;
    const bool active = (j < S_DIM);

    float sp[10];
    float pc1 = 1.0f, pc2 = 1.0f;     // 1 - prob_c  (>= 0, offset folded in)
    if (active) {
        const float* g = strokes + ((size_t)b * S_DIM + j) * 10;
        #pragma unroll
        for (int d = 0; d < 10; d++) { sp[d] = g[d]; sh_strokes[j * 10 + d] = sp[d]; }

        const float* lg = logits + ((size_t)b * S_DIM + j) * 3;
        float l0 = lg[0], l1 = lg[1], l2 = lg[2];
        float mx = fmaxf(l0, fmaxf(l1, l2));
        float e0 = expf(l0 - mx), e1 = expf(l1 - mx), e2 = expf(l2 - mx);
        float s  = e0 + e1 + e2;
        pc1 = 1.0f - (e1 / s);
        pc2 = 1.0f - (e2 / s);
        float lse = mx + logf(s);
        sh_nll[j * 3 + 0] = lse - l0;
        sh_nll[j * 3 + 1] = lse - l1;
        sh_nll[j * 3 + 2] = lse - l2;
    }
    for (int p = tid; p < S_DIM; p += NTHREADS) sh_tc[p] = 0;
    for (int p = tid; p < SPAD; p += NTHREADS)  { sh_row4col[p] = -1; sh_owner[p] = 0x7fffffff; }
    for (int p = tid; p < G_DIM; p += NTHREADS) sh_col4row[p] = -1;
    __syncthreads();

    const int nv = sh_nv;

    // ---- Phase 1: gather valid target params (stride 12) ----
    for (int k = tid; k < nv * 10; k += NTHREADS) {
        int i = k / 10, d = k - i * 10;
        sh_tpv[i * 12 + d] = tparams[((size_t)b * G_DIM + sh_valid[i]) * 10 + d];
    }
    __syncthreads();

    // ---- Phase 2: cost build, column-per-thread (all entries >= 0) ----
    for (int i = 0; i < nv; i++) {
        float4 t0 = *(const float4*)&sh_tpv[i * 12 + 0];
        float4 t1 = *(const float4*)&sh_tpv[i * 12 + 4];
        float  t8 = sh_tpv[i * 12 + 8];
        float  t9 = sh_tpv[i * 12 + 9];
        float acc;
        if (active) {
            acc = (sh_cls[i] == 1) ? pc1 : pc2;
            acc += 7.0f * fabsf(sp[0] - t0.x);
            acc += 7.0f * fabsf(sp[1] - t0.y);
            acc += 5.0f * fabsf(sp[2] - t0.z);
            acc += 5.0f * fabsf(sp[3] - t0.w);
            acc += 5.0f * fabsf(sp[4] - t1.x);
            acc += 5.0f * fabsf(sp[5] - t1.y);
            acc += 5.0f * fabsf(sp[6] - t1.z);
            acc += 5.0f * fabsf(sp[7] - t1.w);
            acc += 2.0f * fabsf(sp[8] - t8);
            acc += 2.0f * fabsf(sp[9] - t9);
        } else {
            acc = BIGC;
        }
        s_C[i * SPAD + j] = acc;
    }
    __syncthreads();

    // ---- Phase 3: row minima (warp per row) -> duals u + greedy candidates ----
    for (int row = wid; row < nv; row += NWARPS) {
        const float* Crow = s_C + row * SPAD;
        unsigned k_[KSLOTS]; int c_[KSLOTS];
        #pragma unroll
        for (int k = 0; k < KSLOTS; k++) {
            k_[k] = __float_as_uint(Crow[lane + 32 * k]);
            c_[k] = lane + 32 * k;
        }
        kmerge(k_[0], c_[0], k_[1], c_[1]);
        kmerge(k_[2], c_[2], k_[3], c_[3]);
        kmerge(k_[4], c_[4], k_[5], c_[5]);
        kmerge(k_[6], c_[6], k_[7], c_[7]);
        kmerge(k_[8], c_[8], k_[9], c_[9]);
        kmerge(k_[0], c_[0], k_[2], c_[2]);
        kmerge(k_[4], c_[4], k_[6], c_[6]);
        kmerge(k_[0], c_[0], k_[4], c_[4]);
        kmerge(k_[0], c_[0], k_[8], c_[8]);

        unsigned g = __reduce_min_sync(0xffffffffu, k_[0]);
        unsigned sel = (k_[0] == g) ? (unsigned)c_[0] : 0xFFFFFFFFu;
        unsigned jm = __reduce_min_sync(0xffffffffu, sel);
        if (lane == 0) { sh_u[row] = __uint_as_float(g); sh_cand[row] = (int)jm; }
    }
    __syncthreads();

    // ---- Phase 4a: parallel greedy conflict resolution (winner = min row) ----
    for (int i = tid; i < nv; i += NTHREADS)
        atomicMin_block(&sh_owner[sh_cand[i]], i);
    __syncthreads();

    if (tid < 32) {
        int base = 0;
        #pragma unroll
        for (int c = 0; c < 4; c++) {
            int i = c * 32 + tid;
            bool isfree = false;
            if (i < nv) {
                int cj = sh_cand[i];
                if (sh_owner[cj] == i) { sh_col4row[i] = cj; sh_row4col[cj] = i; }
                else isfree = true;
            }
            unsigned bal = __ballot_sync(0xffffffffu, isfree);
            if (isfree) {
                int rank = base + __popc(bal & ((1u << tid) - 1u));
                sh_free[rank] = i;
            }
            base += __popc(bal);
        }
        if (tid == 0) sh_nf = base;
    }
    __syncthreads();

    // ---- Phase 4b: Dijkstra augmentations (warp 0, raw-bit keys) ----
    if (tid < 32) {
        const int nf = sh_nf;
        float v_[KSLOTS];
        #pragma unroll
        for (int k = 0; k < KSLOTS; k++) v_[k] = 0.0f;

        for (int f = 0; f < nf; f++) {
            const int cur = sh_free[f];
            float shortest[KSLOTS];
            unsigned scmask = 0;
            #pragma unroll
            for (int k = 0; k < KSLOTS; k++) shortest[k] = 3.0e38f;

            int   i      = cur;
            float u_i    = sh_u[cur];
            const float* Crow = s_C + i * SPAD;
            float minVal = 0.0f;
            int   t      = 0;
            int   sink   = -1;

            while (true) {
                float base = minVal - u_i;

                unsigned k_[KSLOTS]; int c_[KSLOTS];
                #pragma unroll
                for (int k = 0; k < KSLOTS; k++) {
                    int col = lane + 32 * k;
                    c_[k] = col;
                    if (!((scmask >> k) & 1u)) {           // SC guard: load-bearing
                        float d = fmaxf(base + Crow[col] - v_[k], 0.0f);
                        if (d < shortest[k]) { shortest[k] = d; sh_path[col] = i; }
                        k_[k] = __float_as_uint(shortest[k]);
                    } else {
                        k_[k] = 0xFFFFFFFFu;
                    }
                }
                kmerge(k_[0], c_[0], k_[1], c_[1]);
                kmerge(k_[2], c_[2], k_[3], c_[3]);
                kmerge(k_[4], c_[4], k_[5], c_[5]);
                kmerge(k_[6], c_[6], k_[7], c_[7]);
                kmerge(k_[8], c_[8], k_[9], c_[9]);
                kmerge(k_[0], c_[0], k_[2], c_[2]);
                kmerge(k_[4], c_[4], k_[6], c_[6]);
                kmerge(k_[0], c_[0], k_[4], c_[4]);
                kmerge(k_[0], c_[0], k_[8], c_[8]);

                unsigned gm = __reduce_min_sync(0xffffffffu, k_[0]);
                unsigned cc = (k_[0] == gm) ? (unsigned)c_[0] : 0xFFFFFFFFu;
                unsigned js = __reduce_min_sync(0xffffffffu, cc);

                minVal = __uint_as_float(gm);
                if (lane == 0) { sh_SR[t] = i; sh_minStep[t] = minVal; }
                if (lane == (int)(js & 31u)) scmask |= 1u << (js >> 5);
                t++;

                int r = sh_row4col[js];
                if (r < 0) { sink = (int)js; break; }
                i = r;
                u_i = sh_u[i];
                Crow = s_C + i * SPAD;
            }
            __syncwarp();

            if (lane == 0) sh_u[cur] += minVal;
            for (int s2 = 1 + lane; s2 < t; s2 += 32)
                sh_u[sh_SR[s2]] += minVal - sh_minStep[s2 - 1];
            #pragma unroll
            for (int k = 0; k < KSLOTS; k++)
                if ((scmask >> k) & 1u) v_[k] -= minVal - shortest[k];
            __syncwarp();

            {
                int jj = sink;
                while (true) {
                    int i2 = sh_path[jj];
                    sh_row4col[jj] = i2;
                    int nxt = sh_col4row[i2];
                    sh_col4row[i2] = jj;
                    if (i2 == cur) break;
                    jj = nxt;
                }
            }
            __syncwarp();
        }
    }
    __syncthreads();

    // ---- Phase 5: target class per slot ----
    for (int k = tid; k < nv; k += NTHREADS)
        sh_tc[sh_col4row[k]] = sh_cls[k];
    __syncthreads();

    // ---- Phase 6: losses (f32 elementwise, f64 accumulate, single barrier) ----
    double ce_num = 0.0, ce_den = 0.0, csum = 0.0, wsum = 0.0;

    for (int s = tid; s < S_DIM; s += NTHREADS) {
        int c = sh_tc[s];
        float nll = sh_nll[s * 3 + c];
        float w = (c == 0) ? 0.1f : 1.0f;
        ce_num += (double)(w * nll);
        ce_den += (double)w;
    }
    for (int k = tid; k < nv; k += NTHREADS) {
        const float* spv = sh_strokes + sh_col4row[k] * 10;
        const float* tp  = sh_tpv + k * 12;
        #pragma unroll
        for (int d8 = 0; d8 < 8; d8++) {
            float ad = fabsf(spv[d8] - tp[d8]);
            float sl = (ad < 0.1f) ? (0.5f * ad * ad / 0.1f) : (ad - 0.05f);
            csum += (double)ad + (double)sl;
        }
        wsum += (double)fabsf(spv[8] - tp[8]) + (double)fabsf(spv[9] - tp[9]);
    }

    #pragma unroll
    for (int off = 16; off; off >>= 1) {
        ce_num += __shfl_down_sync(0xffffffffu, ce_num, off);
        ce_den += __shfl_down_sync(0xffffffffu, ce_den, off);
        csum   += __shfl_down_sync(0xffffffffu, csum,   off);
        wsum   += __shfl_down_sync(0xffffffffu, wsum,   off);
    }
    if (lane == 0) {
        sh_acc[wid * 4 + 0] = ce_num;
        sh_acc[wid * 4 + 1] = ce_den;
        sh_acc[wid * 4 + 2] = csum;
        sh_acc[wid * 4 + 3] = wsum;
    }
    __syncthreads();

    // ---- Phase 7: per-batch partials + fused finalize (last block) ----
    if (tid == 0) {
        double a0 = 0.0, a1 = 0.0, a2 = 0.0, a3 = 0.0;
        #pragma unroll
        for (int w = 0; w < NWARPS; w++) {
            a0 += sh_acc[w * 4 + 0];
            a1 += sh_acc[w * 4 + 1];
            a2 += sh_acc[w * 4 + 2];
            a3 += sh_acc[w * 4 + 3];
        }
        g_part[b * 5 + 0] = a0;
        g_part[b * 5 + 1] = a1;
        g_part[b * 5 + 2] = a2;
        g_part[b * 5 + 3] = a3;
        g_part[b * 5 + 4] = (double)nv;
        __threadfence();
        unsigned old = atomicInc(&g_done, gridDim.x - 1);
        sh_last = (old == gridDim.x - 1) ? 1 : 0;
    }
    __syncthreads();

    if (sh_last && tid < 32) {
        __threadfence();
        const volatile double* gp = g_part;
        double a0 = 0.0, a1 = 0.0, a2 = 0.0, a3 = 0.0, a4 = 0.0;
        for (int bb = lane; bb < (int)gridDim.x; bb += 32) {
            a0 += gp[bb * 5 + 0];
            a1 += gp[bb * 5 + 1];
            a2 += gp[bb * 5 + 2];
            a3 += gp[bb * 5 + 3];
            a4 += gp[bb * 5 + 4];
        }
        #pragma unroll
        for (int off = 16; off; off >>= 1) {
            a0 += __shfl_down_sync(0xffffffffu, a0, off);
            a1 += __shfl_down_sync(0xffffffffu, a1, off);
            a2 += __shfl_down_sync(0xffffffffu, a2, off);
            a3 += __shfl_down_sync(0xffffffffu, a3, off);
            a4 += __shfl_down_sync(0xffffffffu, a4, off);
        }
        if (lane == 0) {
            double denom = a4 > 1.0 ? a4 : 1.0;
            double loss = CLASS_W * (a0 / a1)
                        + COORD_W * (a2 / denom)
                        + WIDTH_W * (a3 / denom);
            out[0] = (float)loss;
        }
    }
}

extern "C" void kernel_launch(void* const* d_in, const int* in_sizes, int n_in,
                              void* d_out, int out_size)
{
    const float* strokes = (const float*)d_in[0];
    const float* logits  = (const float*)d_in[1];
    const float* tparams = (const float*)d_in[2];
    const int*   tlabels = (const int*)d_in[3];

    int B = in_sizes[3] / G_DIM;
    if (B > B_MAX) B = B_MAX;

    const int dyn_smem = G_DIM * SPAD * (int)sizeof(float);   // 128000 B
    cudaFuncSetAttribute(detr_batch_kernel,
                         cudaFuncAttributeMaxDynamicSharedMemorySize, dyn_smem);

    detr_batch_kernel<<<B, NTHREADS, dyn_smem>>>(strokes, logits, tparams, tlabels,
                                                 (float*)d_out);
}

// round 7
// speedup vs baseline: 5.1077x; 1.3395x over previous
#include <cuda_runtime.h>
#include <math.h>

// Problem constants (fixed by setup_inputs: B=128, S=300, G=100)
#define S_DIM 300
#define SPAD  320
#define G_DIM 100
#define B_MAX 128
#define NTHREADS 320
#define NWARPS (NTHREADS / 32)
#define KSLOTS 10
#define BIGC  1.0e30f
#define FREECAP 256

#define CLASS_W 1.0
#define COORD_W 5.0
#define WIDTH_W 2.0
#define P0_W    2.0

static __device__ double   g_part[B_MAX * 5];
static __device__ unsigned g_done = 0;

// All costs carry a +1.0f offset so every entry is >= 0, and v only ever
// decreases (v <= 0), so C - v >= 0 and reduced Dijkstra distances >= 0.
// For non-negative IEEE floats raw bits are order-isomorphic to values, so
// argmin keys are plain __float_as_uint(x).

extern __shared__ float s_C[];    // [G_DIM * SPAD] f32 cost matrix (128 KB)

// pairwise merge preferring LEFT on ties (left = smaller column)
__device__ __forceinline__ void kmerge(unsigned& kL, int& cL, unsigned kR, int cR) {
    if (kR < kL) { kL = kR; cL = cR; }
}

__global__ __launch_bounds__(NTHREADS, 1)
void detr_batch_kernel(const float* __restrict__ strokes,
                       const float* __restrict__ logits,
                       const float* __restrict__ tparams,
                       const int*   __restrict__ tlabels,
                       float* __restrict__ out)
{
    const int b    = blockIdx.x;
    const int tid  = threadIdx.x;
    const int wid  = tid >> 5;
    const int lane = tid & 31;

    __shared__ float  sh_strokes[S_DIM * 10];
    __shared__ float  sh_tpv[G_DIM * 12];
    __shared__ float  sh_nll[S_DIM * 3];
    __shared__ float  sh_u[G_DIM];
    __shared__ float  sh_minStep[G_DIM + 4];
    __shared__ int    sh_row4col[SPAD];
    __shared__ int    sh_col4row[G_DIM];
    __shared__ int    sh_path[SPAD];
    __shared__ int    sh_SR[G_DIM + 4];
    __shared__ int    sh_valid[G_DIM];
    __shared__ int    sh_cls[G_DIM];
    __shared__ int    sh_cand[G_DIM];
    __shared__ int    sh_free[FREECAP];
    __shared__ int    sh_dij[FREECAP];
    __shared__ int    sh_owner[SPAD];
    __shared__ int    sh_tc[S_DIM];
    __shared__ int    sh_nv, sh_nf, sh_last;
    __shared__ double sh_acc[NWARPS * 4];

    // ---- Phase 0 (warp 0): valid-target compaction; all: staging ----
    if (tid < 32) {
        int base = 0;
        #pragma unroll
        for (int c = 0; c < 4; c++) {
            int g = c * 32 + tid;
            int l = (g < G_DIM) ? tlabels[(size_t)b * G_DIM + g] : 0;
            unsigned bal = __ballot_sync(0xffffffffu, l > 0);
            if (l > 0) {
                int rank = base + __popc(bal & ((1u << tid) - 1u));
                sh_valid[rank] = g;
                sh_cls[rank]   = l;
            }
            base += __popc(bal);
        }
        if (tid == 0) sh_nv = base;
    }

    const int j = tid;
    const bool active = (j < S_DIM);

    float sp[10];
    float pc1 = 1.0f, pc2 = 1.0f;     // 1 - prob_c  (>= 0, offset folded in)
    if (active) {
        const float* g = strokes + ((size_t)b * S_DIM + j) * 10;
        #pragma unroll
        for (int d = 0; d < 10; d++) { sp[d] = g[d]; sh_strokes[j * 10 + d] = sp[d]; }

        const float* lg = logits + ((size_t)b * S_DIM + j) * 3;
        float l0 = lg[0], l1 = lg[1], l2 = lg[2];
        float mx = fmaxf(l0, fmaxf(l1, l2));
        float e0 = expf(l0 - mx), e1 = expf(l1 - mx), e2 = expf(l2 - mx);
        float s  = e0 + e1 + e2;
        pc1 = 1.0f - (e1 / s);
        pc2 = 1.0f - (e2 / s);
        float lse = mx + logf(s);
        sh_nll[j * 3 + 0] = lse - l0;
        sh_nll[j * 3 + 1] = lse - l1;
        sh_nll[j * 3 + 2] = lse - l2;
    }
    for (int p = tid; p < S_DIM; p += NTHREADS) sh_tc[p] = 0;
    for (int p = tid; p < SPAD; p += NTHREADS)  { sh_row4col[p] = -1; sh_owner[p] = 0x7fffffff; }
    for (int p = tid; p < G_DIM; p += NTHREADS) sh_col4row[p] = -1;
    __syncthreads();

    const int nv = sh_nv;

    // ---- Phase 1: gather valid target params (stride 12) ----
    for (int k = tid; k < nv * 10; k += NTHREADS) {
        int i = k / 10, d = k - i * 10;
        sh_tpv[i * 12 + d] = tparams[((size_t)b * G_DIM + sh_valid[i]) * 10 + d];
    }
    __syncthreads();

    // ---- Phase 2: cost build, column-per-thread (all entries >= 0) ----
    for (int i = 0; i < nv; i++) {
        float4 t0 = *(const float4*)&sh_tpv[i * 12 + 0];
        float4 t1 = *(const float4*)&sh_tpv[i * 12 + 4];
        float  t8 = sh_tpv[i * 12 + 8];
        float  t9 = sh_tpv[i * 12 + 9];
        float acc;
        if (active) {
            acc = (sh_cls[i] == 1) ? pc1 : pc2;
            acc += 7.0f * fabsf(sp[0] - t0.x);
            acc += 7.0f * fabsf(sp[1] - t0.y);
            acc += 5.0f * fabsf(sp[2] - t0.z);
            acc += 5.0f * fabsf(sp[3] - t0.w);
            acc += 5.0f * fabsf(sp[4] - t1.x);
            acc += 5.0f * fabsf(sp[5] - t1.y);
            acc += 5.0f * fabsf(sp[6] - t1.z);
            acc += 5.0f * fabsf(sp[7] - t1.w);
            acc += 2.0f * fabsf(sp[8] - t8);
            acc += 2.0f * fabsf(sp[9] - t9);
        } else {
            acc = BIGC;
        }
        s_C[i * SPAD + j] = acc;
    }
    __syncthreads();

    // ---- Phase 3: row minima (warp per row) -> duals u + greedy candidates ----
    for (int row = wid; row < nv; row += NWARPS) {
        const float* Crow = s_C + row * SPAD;
        unsigned k_[KSLOTS]; int c_[KSLOTS];
        #pragma unroll
        for (int k = 0; k < KSLOTS; k++) {
            k_[k] = __float_as_uint(Crow[lane + 32 * k]);
            c_[k] = lane + 32 * k;
        }
        kmerge(k_[0], c_[0], k_[1], c_[1]);
        kmerge(k_[2], c_[2], k_[3], c_[3]);
        kmerge(k_[4], c_[4], k_[5], c_[5]);
        kmerge(k_[6], c_[6], k_[7], c_[7]);
        kmerge(k_[8], c_[8], k_[9], c_[9]);
        kmerge(k_[0], c_[0], k_[2], c_[2]);
        kmerge(k_[4], c_[4], k_[6], c_[6]);
        kmerge(k_[0], c_[0], k_[4], c_[4]);
        kmerge(k_[0], c_[0], k_[8], c_[8]);

        unsigned g = __reduce_min_sync(0xffffffffu, k_[0]);
        unsigned sel = (k_[0] == g) ? (unsigned)c_[0] : 0xFFFFFFFFu;
        unsigned jm = __reduce_min_sync(0xffffffffu, sel);
        if (lane == 0) { sh_u[row] = __uint_as_float(g); sh_cand[row] = (int)jm; }
    }
    __syncthreads();

    // ---- Phase 4a: parallel greedy conflict resolution (winner = min row) ----
    for (int i = tid; i < nv; i += NTHREADS)
        atomicMin_block(&sh_owner[sh_cand[i]], i);
    __syncthreads();

    if (tid < 32) {
        int base = 0;
        #pragma unroll
        for (int c = 0; c < 4; c++) {
            int i = c * 32 + tid;
            bool isfree = false;
            if (i < nv) {
                int cj = sh_cand[i];
                if (sh_owner[cj] == i) { sh_col4row[i] = cj; sh_row4col[cj] = i; }
                else isfree = true;
            }
            unsigned bal = __ballot_sync(0xffffffffu, isfree);
            if (isfree) {
                int rank = base + __popc(bal & ((1u << tid) - 1u));
                sh_free[rank] = i;
            }
            base += __popc(bal);
        }
        if (tid == 0) sh_nf = base;
    }
    __syncthreads();

    // ---- Phase 4b: warp 0 — ARR (LAPJV augmenting row reduction) + Dijkstra ----
    if (tid < 32) {
        float v_[KSLOTS];                  // column duals, v <= 0 always
        #pragma unroll
        for (int k = 0; k < KSLOTS; k++) v_[k] = 0.0f;

        // ---- ARR: for each free row, min1/min2 of (C - v); assign tightly ----
        int h = 0, t = sh_nf, nd = 0;
        int ops = 0;
        const int cap = 2 * nv + 8;
        while (h < t) {
            if (ops >= cap || t >= FREECAP - 1) {
                // overflow / cap: remaining rows go straight to Dijkstra
                for (int q = h + (int)lane; q < t; q += 32)
                    sh_dij[nd + (q - h)] = sh_free[q];
                nd += t - h;
                break;
            }
            ops++;
            const int i = sh_free[h++];
            const float* Crow = s_C + i * SPAD;

            unsigned m1 = 0xFFFFFFFFu, m2 = 0xFFFFFFFFu; int c1 = 0;
            #pragma unroll
            for (int k = 0; k < KSLOTS; k++) {
                unsigned x = __float_as_uint(Crow[lane + 32 * k] - v_[k]);
                if (x < m1) { m2 = m1; m1 = x; c1 = lane + 32 * k; }
                else if (x < m2) m2 = x;
            }
            unsigned g1 = __reduce_min_sync(0xffffffffu, m1);
            unsigned bal = __ballot_sync(0xffffffffu, m1 == g1);
            int winlane = __ffs(bal) - 1;
            unsigned cand = (lane == winlane) ? m2 : m1;
            unsigned g2 = __reduce_min_sync(0xffffffffu, cand);
            int j1 = __shfl_sync(0xffffffffu, c1, winlane);

            int owner = sh_row4col[j1];
            if (g1 == g2 && owner >= 0) {   // exact tie on occupied col: defer
                if (lane == 0) sh_dij[nd] = i;
                nd++;
                continue;
            }
            float min1 = __uint_as_float(g1);
            float min2 = __uint_as_float(g2);
            sh_u[i] = min2;                              // lockstep same-value write
            if (g1 != g2 && lane == (j1 & 31))
                v_[j1 >> 5] -= (min2 - min1);            // tighten new arc
            sh_row4col[j1] = i;
            sh_col4row[i] = j1;
            if (owner >= 0) {
                sh_col4row[owner] = -1;
                sh_free[t++] = owner;                    // displaced row re-queued
            }
            __syncwarp();
        }
        __syncwarp();

        // ---- Dijkstra augmentation for the leftover rows ----
        for (int f = 0; f < nd; f++) {
            const int cur = sh_dij[f];
            float shortest[KSLOTS];
            unsigned scmask = 0;
            #pragma unroll
            for (int k = 0; k < KSLOTS; k++) shortest[k] = 3.0e38f;

            int   i      = cur;
            float u_i    = sh_u[cur];
            const float* Crow = s_C + i * SPAD;
            float minVal = 0.0f;
            int   tt     = 0;
            int   sink   = -1;

            while (true) {
                float base = minVal - u_i;

                unsigned k_[KSLOTS]; int c_[KSLOTS];
                #pragma unroll
                for (int k = 0; k < KSLOTS; k++) {
                    int col = lane + 32 * k;
                    c_[k] = col;
                    if (!((scmask >> k) & 1u)) {           // SC guard: load-bearing
                        float d = fmaxf(base + Crow[col] - v_[k], 0.0f);
                        if (d < shortest[k]) { shortest[k] = d; sh_path[col] = i; }
                        k_[k] = __float_as_uint(shortest[k]);
                    } else {
                        k_[k] = 0xFFFFFFFFu;
                    }
                }
                kmerge(k_[0], c_[0], k_[1], c_[1]);
                kmerge(k_[2], c_[2], k_[3], c_[3]);
                kmerge(k_[4], c_[4], k_[5], c_[5]);
                kmerge(k_[6], c_[6], k_[7], c_[7]);
                kmerge(k_[8], c_[8], k_[9], c_[9]);
                kmerge(k_[0], c_[0], k_[2], c_[2]);
                kmerge(k_[4], c_[4], k_[6], c_[6]);
                kmerge(k_[0], c_[0], k_[4], c_[4]);
                kmerge(k_[0], c_[0], k_[8], c_[8]);

                unsigned gm = __reduce_min_sync(0xffffffffu, k_[0]);
                unsigned cc = (k_[0] == gm) ? (unsigned)c_[0] : 0xFFFFFFFFu;
                unsigned js = __reduce_min_sync(0xffffffffu, cc);

                minVal = __uint_as_float(gm);
                if (lane == 0) { sh_SR[tt] = i; sh_minStep[tt] = minVal; }
                if (lane == (int)(js & 31u)) scmask |= 1u << (js >> 5);
                tt++;

                int r = sh_row4col[js];
                if (r < 0) { sink = (int)js; break; }
                i = r;
                u_i = sh_u[i];
                Crow = s_C + i * SPAD;
            }
            __syncwarp();

            if (lane == 0) sh_u[cur] += minVal;
            for (int s2 = 1 + lane; s2 < tt; s2 += 32)
                sh_u[sh_SR[s2]] += minVal - sh_minStep[s2 - 1];
            #pragma unroll
            for (int k = 0; k < KSLOTS; k++)
                if ((scmask >> k) & 1u) v_[k] -= minVal - shortest[k];
            __syncwarp();

            {
                int jj = sink;
                while (true) {
                    int i2 = sh_path[jj];
                    sh_row4col[jj] = i2;
                    int nxt = sh_col4row[i2];
                    sh_col4row[i2] = jj;
                    if (i2 == cur) break;
                    jj = nxt;
                }
            }
            __syncwarp();
        }
    }
    __syncthreads();

    // ---- Phase 5: target class per slot ----
    for (int k = tid; k < nv; k += NTHREADS)
        sh_tc[sh_col4row[k]] = sh_cls[k];
    __syncthreads();

    // ---- Phase 6: losses (f32 elementwise, f64 accumulate, single barrier) ----
    double ce_num = 0.0, ce_den = 0.0, csum = 0.0, wsum = 0.0;

    for (int s = tid; s < S_DIM; s += NTHREADS) {
        int c = sh_tc[s];
        float nll = sh_nll[s * 3 + c];
        float w = (c == 0) ? 0.1f : 1.0f;
        ce_num += (double)(w * nll);
        ce_den += (double)w;
    }
    for (int k = tid; k < nv; k += NTHREADS) {
        const float* spv = sh_strokes + sh_col4row[k] * 10;
        const float* tp  = sh_tpv + k * 12;
        #pragma unroll
        for (int d8 = 0; d8 < 8; d8++) {
            float ad = fabsf(spv[d8] - tp[d8]);
            float sl = (ad < 0.1f) ? (0.5f * ad * ad / 0.1f) : (ad - 0.05f);
            csum += (double)ad + (double)sl;
        }
        wsum += (double)fabsf(spv[8] - tp[8]) + (double)fabsf(spv[9] - tp[9]);
    }

    #pragma unroll
    for (int off = 16; off; off >>= 1) {
        ce_num += __shfl_down_sync(0xffffffffu, ce_num, off);
        ce_den += __shfl_down_sync(0xffffffffu, ce_den, off);
        csum   += __shfl_down_sync(0xffffffffu, csum,   off);
        wsum   += __shfl_down_sync(0xffffffffu, wsum,   off);
    }
    if (lane == 0) {
        sh_acc[wid * 4 + 0] = ce_num;
        sh_acc[wid * 4 + 1] = ce_den;
        sh_acc[wid * 4 + 2] = csum;
        sh_acc[wid * 4 + 3] = wsum;
    }
    __syncthreads();

    // ---- Phase 7: per-batch partials + fused finalize (last block) ----
    if (tid == 0) {
        double a0 = 0.0, a1 = 0.0, a2 = 0.0, a3 = 0.0;
        #pragma unroll
        for (int w = 0; w < NWARPS; w++) {
            a0 += sh_acc[w * 4 + 0];
            a1 += sh_acc[w * 4 + 1];
            a2 += sh_acc[w * 4 + 2];
            a3 += sh_acc[w * 4 + 3];
        }
        g_part[b * 5 + 0] = a0;
        g_part[b * 5 + 1] = a1;
        g_part[b * 5 + 2] = a2;
        g_part[b * 5 + 3] = a3;
        g_part[b * 5 + 4] = (double)nv;
        __threadfence();
        unsigned old = atomicInc(&g_done, gridDim.x - 1);
        sh_last = (old == gridDim.x - 1) ? 1 : 0;
    }
    __syncthreads();

    if (sh_last && tid < 32) {
        __threadfence();
        const volatile double* gp = g_part;
        double a0 = 0.0, a1 = 0.0, a2 = 0.0, a3 = 0.0, a4 = 0.0;
        for (int bb = lane; bb < (int)gridDim.x; bb += 32) {
            a0 += gp[bb * 5 + 0];
            a1 += gp[bb * 5 + 1];
            a2 += gp[bb * 5 + 2];
            a3 += gp[bb * 5 + 3];
            a4 += gp[bb * 5 + 4];
        }
        #pragma unroll
        for (int off = 16; off; off >>= 1) {
            a0 += __shfl_down_sync(0xffffffffu, a0, off);
            a1 += __shfl_down_sync(0xffffffffu, a1, off);
            a2 += __shfl_down_sync(0xffffffffu, a2, off);
            a3 += __shfl_down_sync(0xffffffffu, a3, off);
            a4 += __shfl_down_sync(0xffffffffu, a4, off);
        }
        if (lane == 0) {
            double denom = a4 > 1.0 ? a4 : 1.0;
            double loss = CLASS_W * (a0 / a1)
                        + COORD_W * (a2 / denom)
                        + WIDTH_W * (a3 / denom);
            out[0] = (float)loss;
        }
    }
}

extern "C" void kernel_launch(void* const* d_in, const int* in_sizes, int n_in,
                              void* d_out, int out_size)
{
    const float* strokes = (const float*)d_in[0];
    const float* logits  = (const float*)d_in[1];
    const float* tparams = (const float*)d_in[2];
    const int*   tlabels = (const int*)d_in[3];

    int B = in_sizes[3] / G_DIM;
    if (B > B_MAX) B = B_MAX;

    const int dyn_smem = G_DIM * SPAD * (int)sizeof(float);   // 128000 B
    cudaFuncSetAttribute(detr_batch_kernel,
                         cudaFuncAttributeMaxDynamicSharedMemorySize, dyn_smem);

    detr_batch_kernel<<<B, NTHREADS, dyn_smem>>>(strokes, logits, tparams, tlabels,
                                                 (float*)d_out);
}